// round 17
// baseline (speedup 1.0000x reference)
#include <cuda_runtime.h>
#include <cstdint>

#define B_DIM 16
#define P_DIM 4096
#define T_DIM 1024
#define NBINS 256                       // 4 classes * 8x8 cells
#define CAP   64                        // max preds per (batch,bin); Binom(4096,1/256) max ~35
#define NTA   512
#define NBLKA ((B_DIM * P_DIM) / NTA)   // 128
#define NTB   1024
#define EIGHTHS 8
#define TPB   (T_DIM / EIGHTHS)         // 128 targets per block
#define LANES 8
#define NBLKB (B_DIM * EIGHTHS)         // 128

// Zero-initialized global scratch; kernel B's last block resets everything,
// so CUDA-graph replays start clean.
__device__ float2   g_xy[B_DIM * NBINS * CAP];    // binned pred coords (2MB)
__device__ unsigned g_pidArr[B_DIM * NBINS * CAP];// binned pred ids (1MB)
__device__ unsigned g_cnt[B_DIM * NBINS];         // bin counters
__device__ unsigned g_mask[B_DIM * (P_DIM / 32)]; // per-batch dedup bitmask
__device__ unsigned g_tp;
__device__ unsigned g_done;

// ---- kernel A: bin all preds once, chip-wide (1 pred/thread) ----
__global__ void __launch_bounds__(NTA, 1)
bin_kernel(const float* __restrict__ pred)
{
    const int gidx = blockIdx.x * NTA + threadIdx.x;   // 0..65535
    const int b = gidx >> 12;
    const int p = gidx & (P_DIM - 1);
    const float* e = pred + (size_t)gidx * 3;
    float c = e[0], x = e[1], y = e[2];
    int cx = min(7, (int)(x * 0.125f));
    int cy = min(7, (int)(y * 0.125f));
    int bin = (int)c * 64 + cy * 8 + cx;
    unsigned slot = atomicAdd(&g_cnt[b * NBINS + bin], 1u);
    int base = (b * NBINS + bin) * CAP + (int)slot;
    g_xy[base] = make_float2(x, y);
    g_pidArr[base] = (unsigned)p;
}

// ---- kernel B: per-target nearest valid pred + dedup + f1 ----
__global__ void __launch_bounds__(NTB, 1)
match_kernel(const float* __restrict__ gt, float* __restrict__ out)
{
    const int b      = blockIdx.x;
    const int eighth = blockIdx.y;
    const int tid    = threadIdx.x;

    __shared__ unsigned s_cnt[NBINS];
    __shared__ int s_last;

    // hoisted target load (overlaps the counter staging)
    const int t = eighth * TPB + (tid >> 3);
    const int h = tid & 7;
    const float* te = gt + ((size_t)b * T_DIM + t) * 3;
    const float tcf = te[0];
    const float tx  = te[1];
    const float ty  = te[2];

    if (tid < NBINS) s_cnt[tid] = g_cnt[b * NBINS + tid];
    __syncthreads();

    int newbit = 0;
    {
        const int   tcls = (int)tcf;
        const int cx0 = max(0, (int)((tx - 5.0f) * 0.125f));
        const int cx1 = min(7, (int)((tx + 5.0f) * 0.125f));
        const int cy0 = max(0, (int)((ty - 5.0f) * 0.125f));
        const int cy1 = min(7, (int)((ty + 5.0f) * 0.125f));

        float bestd2  = __int_as_float(0x7f800000);
        int   bestidx = 0;
        for (int cy = cy0; cy <= cy1; cy++) {
            for (int cx = cx0; cx <= cx1; cx++) {
                const int bin = tcls * 64 + cy * 8 + cx;
                const unsigned cnt = s_cnt[bin];
                const int base = (b * NBINS + bin) * CAP;
                for (unsigned s = h; s < cnt; s += LANES) {
                    float2 q = g_xy[base + (int)s];    // L1-resident after first touch
                    float dx = q.x - tx;
                    float dy = q.y - ty;
                    float d2 = fmaf(dx, dx, dy * dy);
                    if (d2 < bestd2) { bestd2 = d2; bestidx = base + (int)s; }
                }
            }
        }
        // combine the 8 lanes (butterfly)
#pragma unroll
        for (int o = 1; o < LANES; o <<= 1) {
            float od2  = __shfl_xor_sync(0xFFFFFFFFu, bestd2, o);
            int   oidx = __shfl_xor_sync(0xFFFFFFFFu, bestidx, o);
            if (od2 < bestd2 || (od2 == bestd2 && oidx < bestidx)) {
                bestd2 = od2; bestidx = oidx;
            }
        }

        if (h == 0 && bestd2 <= 25.0f) {
            unsigned p   = g_pidArr[bestidx];
            unsigned bit = 1u << (p & 31u);
            unsigned old = atomicOr(&g_mask[b * (P_DIM / 32) + (p >> 5)], bit);
            newbit = (old & bit) ? 0 : 1;
        }
    }
    int cnt = __syncthreads_count(newbit);

    if (tid == 0) {
        if (cnt) atomicAdd(&g_tp, (unsigned)cnt);
        __threadfence();
        s_last = (atomicAdd(&g_done, 1u) == NBLKB - 1);
    }
    __syncthreads();
    if (!s_last) return;

    // ---- last block: f1 + reset ALL scratch for the next graph replay ----
    __threadfence();
    for (int i = tid; i < B_DIM * (P_DIM / 32); i += NTB) g_mask[i] = 0u;
    for (int i = tid; i < B_DIM * NBINS; i += NTB)        g_cnt[i]  = 0u;
    if (tid == 0) {
        float tp = (float)atomicAdd(&g_tp, 0u);
        float fp = (float)(B_DIM * P_DIM) - tp;
        float fn = (float)(B_DIM * T_DIM) - tp;
        const float eps = 1e-6f;
        float precision = (tp + eps) / (tp + eps + fp + eps);
        float recall    = (tp + eps) / (tp + fn + eps);
        float f1 = 2.0f * precision * recall / (precision + recall);
        out[0] = 1.0f - f1;
        g_tp = 0u;
        g_done = 0u;
    }
}

extern "C" void kernel_launch(void* const* d_in, const int* in_sizes, int n_in,
                              void* d_out, int out_size) {
    const float* pred = (const float*)d_in[0];
    const float* gt   = (const float*)d_in[1];
    if (n_in >= 2 && in_sizes[0] == B_DIM * T_DIM * 3) {   // swapped-order guard
        pred = (const float*)d_in[1];
        gt   = (const float*)d_in[0];
    }
    float* out = (float*)d_out;

    bin_kernel<<<NBLKA, NTA>>>(pred);
    dim3 gridB(B_DIM, EIGHTHS);
    match_kernel<<<gridB, NTB>>>(gt, out);
}